// round 1
// baseline (speedup 1.0000x reference)
#include <cuda_runtime.h>
#include <math.h>
#include <stdint.h>

// ----------------------------------------------------------------------------
// Problem constants
// ----------------------------------------------------------------------------
#define WAY   100
#define SHOT  5
#define DIM   2048
#define NQ    10000
#define KSEL  512

// ----------------------------------------------------------------------------
// Static device scratch (no allocations allowed)
// ----------------------------------------------------------------------------
// float buffer layout (offsets in floats)
#define O_P0R   0                       // 100*2048
#define O_P0D   (O_P0R + WAY*DIM)
#define O_P1    (O_P0D + WAY*DIM)
#define O_QNR   (O_P1  + WAY*DIM)       // 10000
#define O_QND   (O_QNR + NQ)
#define O_GR    (O_QND + NQ)            // 10000*100
#define O_GD    (O_GR  + NQ*WAY)
#define O_G2    (O_GD  + NQ*WAY)
#define O_LH    (O_G2  + NQ*WAY)
#define O_LL    (O_LH  + NQ*WAY)
#define O_CERT  (O_LL  + NQ*WAY)        // 10000
#define O_SELV  (O_CERT + NQ)           // 512
#define O_ABSR  (O_SELV + KSEL)
#define O_ABSD  (O_ABSR + NQ)
#define O_RELR  (O_ABSD + NQ)
#define O_RELD  (O_RELR + NQ)
#define O_CN1   (O_RELD + NQ)           // 100 each
#define O_SC1   (O_CN1 + WAY)
#define O_CN2   (O_SC1 + WAY)
#define O_SC2   (O_CN2 + WAY)
#define O_SCH   (O_SC2 + WAY)
#define O_SCL   (O_SCH + WAY)
#define O_KL    (O_SCL + WAY)
#define BUF_FLOATS (O_KL + WAY)

__device__ float g_buf[BUF_FLOATS];

// int buffer layout
#define IO_RES   0         // 10000
#define IO_DCT   10000     // 10000
#define IO_SELI  20000     // 512
#define IO_PSE   20512     // 512
#define IO_SELK  21024     // 1
#define IO_CNTS  21025     // 2 : R, D
#define IBUF_INTS 21027

__device__ int g_ibuf[IBUF_INTS];
__device__ int g_fullCnt = NQ;

// ----------------------------------------------------------------------------
// Block reduction helpers (blockDim == 256, deterministic fixed tree)
// ----------------------------------------------------------------------------
__device__ __forceinline__ float blockReduceSum256(float v, float* s) {
    int t = threadIdx.x;
    __syncthreads();
    s[t] = v; __syncthreads();
    #pragma unroll
    for (int o = 128; o > 0; o >>= 1) {
        if (t < o) s[t] += s[t + o];
        __syncthreads();
    }
    float r = s[0];
    __syncthreads();
    return r;
}

__device__ __forceinline__ float blockReduceMax256(float v, float* s) {
    int t = threadIdx.x;
    __syncthreads();
    s[t] = v; __syncthreads();
    #pragma unroll
    for (int o = 128; o > 0; o >>= 1) {
        if (t < o) s[t] = fmaxf(s[t], s[t + o]);
        __syncthreads();
    }
    float r = s[0];
    __syncthreads();
    return r;
}

// Exclusive scan of 0/1 flags over 1024 threads (stable, deterministic).
// ws must have >= 32 ints. Returns exclusive prefix; *tot gets the total.
__device__ __forceinline__ int blockScan1024(int v, int* tot, int* ws) {
    int t = threadIdx.x;
    int lane = t & 31, w = t >> 5;
    int x = v;
    #pragma unroll
    for (int o = 1; o < 32; o <<= 1) {
        int y = __shfl_up_sync(0xffffffffu, x, o);
        if (lane >= o) x += y;
    }
    if (lane == 31) ws[w] = x;
    __syncthreads();
    if (w == 0) {
        int s2 = ws[lane];
        #pragma unroll
        for (int o = 1; o < 32; o <<= 1) {
            int y = __shfl_up_sync(0xffffffffu, s2, o);
            if (lane >= o) s2 += y;
        }
        ws[lane] = s2;
    }
    __syncthreads();
    int base = (w > 0) ? ws[w - 1] : 0;
    int excl = base + x - v;
    *tot = ws[31];
    __syncthreads();
    return excl;
}

__device__ __forceinline__ unsigned orderedKey(float f) {
    unsigned u = __float_as_uint(f);
    return (u & 0x80000000u) ? ~u : (u | 0x80000000u);
}

// ----------------------------------------------------------------------------
// K1: proto0[c,:] = l2norm(mean over shots)
// ----------------------------------------------------------------------------
__global__ void k_proto0(const float* __restrict__ shot, float* __restrict__ proto) {
    int c = blockIdx.x;
    __shared__ float red[256];
    float ssq = 0.f;
    for (int d = threadIdx.x; d < DIM; d += 256) {
        float m = 0.f;
        #pragma unroll
        for (int s = 0; s < SHOT; s++) m += shot[((size_t)c * SHOT + s) * DIM + d];
        m = m / (float)SHOT;
        proto[(size_t)c * DIM + d] = m;
        ssq += m * m;
    }
    float tot = blockReduceSum256(ssq, red);
    __shared__ float inv;
    if (threadIdx.x == 0) inv = 1.0f / fmaxf(sqrtf(tot), 1e-12f);
    __syncthreads();
    for (int d = threadIdx.x; d < DIM; d += 256)
        proto[(size_t)c * DIM + d] *= inv;
}

// ----------------------------------------------------------------------------
// K2: per-row query norm (clamped)
// ----------------------------------------------------------------------------
__global__ void k_qnorm(const float* __restrict__ X, float* __restrict__ qn) {
    int q = blockIdx.x;
    __shared__ float red[256];
    const float* row = X + (size_t)q * DIM;
    float ssq = 0.f;
    for (int d = threadIdx.x; d < DIM; d += 256) { float v = row[d]; ssq += v * v; }
    float tot = blockReduceSum256(ssq, red);
    if (threadIdx.x == 0) qn[q] = fmaxf(sqrtf(tot), 1e-12f);
}

// ----------------------------------------------------------------------------
// K3: GEMM  C[j,c] = dot(A[row_j,:], P[c,:]) / qn[row_j]
//     row_j = map ? map[j] : j ; j < *cnt ; ldc = 100
// ----------------------------------------------------------------------------
#define G_TQ 64
#define G_KC 32
__global__ __launch_bounds__(256) void k_gemm(
    const float* __restrict__ A, const float* __restrict__ qn,
    const float* __restrict__ P, float* __restrict__ C,
    const int* __restrict__ map, const int* __restrict__ cnt)
{
    int Q = *cnt;
    int rowBase = blockIdx.x * G_TQ;
    if (rowBase >= Q) return;

    __shared__ float As[G_TQ][G_KC + 1];
    __shared__ float Bs[112][G_KC + 1];

    int tx = threadIdx.x & 15, ty = threadIdx.x >> 4;  // 16 x 16
    float acc[4][7];
    #pragma unroll
    for (int i = 0; i < 4; i++)
        #pragma unroll
        for (int j = 0; j < 7; j++) acc[i][j] = 0.f;

    for (int k0 = 0; k0 < DIM; k0 += G_KC) {
        // stage A tile (64 x 32)
        #pragma unroll
        for (int t = threadIdx.x; t < G_TQ * G_KC; t += 256) {
            int r = t / G_KC, k = t % G_KC;
            int j = rowBase + r;
            float v = 0.f;
            if (j < Q) {
                int gq = map ? map[j] : j;
                v = A[(size_t)gq * DIM + k0 + k];
            }
            As[r][k] = v;
        }
        // stage B tile (112 x 32, rows >= 100 zeroed)
        for (int t = threadIdx.x; t < 112 * G_KC; t += 256) {
            int c = t / G_KC, k = t % G_KC;
            Bs[c][k] = (c < WAY) ? P[(size_t)c * DIM + k0 + k] : 0.f;
        }
        __syncthreads();
        #pragma unroll
        for (int kk = 0; kk < G_KC; kk++) {
            float a0 = As[ty * 4 + 0][kk];
            float a1 = As[ty * 4 + 1][kk];
            float a2 = As[ty * 4 + 2][kk];
            float a3 = As[ty * 4 + 3][kk];
            #pragma unroll
            for (int jj = 0; jj < 7; jj++) {
                float b = Bs[tx + 16 * jj][kk];
                acc[0][jj] += a0 * b;
                acc[1][jj] += a1 * b;
                acc[2][jj] += a2 * b;
                acc[3][jj] += a3 * b;
            }
        }
        __syncthreads();
    }
    #pragma unroll
    for (int i = 0; i < 4; i++) {
        int j = rowBase + ty * 4 + i;
        if (j < Q) {
            int gq = map ? map[j] : j;
            float inv = 1.0f / qn[gq];
            #pragma unroll
            for (int jj = 0; jj < 7; jj++) {
                int c = tx + 16 * jj;
                if (c < WAY) C[(size_t)j * WAY + c] = acc[i][jj] * inv;
            }
        }
    }
}

// ----------------------------------------------------------------------------
// K4: column L2 norm over (possibly gathered) rows
// ----------------------------------------------------------------------------
__global__ void k_colnorm(const float* __restrict__ C, const int* __restrict__ map,
                          const int* __restrict__ cnt, float* __restrict__ cn)
{
    int c = blockIdx.x;
    int Q = *cnt;
    __shared__ float red[256];
    float ssq = 0.f;
    for (int j = threadIdx.x; j < Q; j += 256) {
        int r = map ? map[j] : j;
        float v = C[(size_t)r * WAY + c];
        ssq += v * v;
    }
    float tot = blockReduceSum256(ssq, red);
    if (threadIdx.x == 0) cn[c] = sqrtf(tot);
}

// scale[c] = tp / (cn[c] + 1e-6)
__global__ void k_scale(const float* __restrict__ cn, const float* __restrict__ tpp,
                        float* __restrict__ sc)
{
    int c = threadIdx.x;
    if (c < WAY) sc[c] = (*tpp) / (cn[c] + 1e-6f);
}

// ----------------------------------------------------------------------------
// K5: cert[j] = max_c C[row_j,c]*scale[c]
// ----------------------------------------------------------------------------
__global__ void k_cert(const float* __restrict__ C, const float* __restrict__ sc,
                       const int* __restrict__ map, const int* __restrict__ cnt,
                       float* __restrict__ cert)
{
    int j = blockIdx.x * blockDim.x + threadIdx.x;
    int Q = *cnt;
    if (j >= Q) return;
    int r = map ? map[j] : j;
    const float* row = C + (size_t)r * WAY;
    float best = -3.4e38f;
    #pragma unroll 4
    for (int c = 0; c < WAY; c++) {
        float v = row[c] * sc[c];
        if (v > best) best = v;
    }
    cert[j] = best;
}

// ----------------------------------------------------------------------------
// K6: single-block radix top-k (k = min(Q,512)), stable by index.
// ----------------------------------------------------------------------------
__global__ __launch_bounds__(1024) void k_topk(
    const float* __restrict__ cert, const int* __restrict__ cnt,
    int* __restrict__ selIdx, float* __restrict__ selVal, int* __restrict__ selK)
{
    const int T = 1024;
    int t = threadIdx.x;
    __shared__ unsigned hist[2048];
    __shared__ int ws[32];
    __shared__ unsigned shPrefix, shMask;
    __shared__ int shRem;
    int Q = *cnt;
    int k = (Q < KSEL) ? Q : KSEL;
    if (t == 0) { shPrefix = 0u; shMask = 0u; shRem = k; }
    __syncthreads();

    for (int pass = 0; pass < 3; pass++) {
        int shift = (pass == 0) ? 21 : ((pass == 1) ? 10 : 0);
        int nb = (pass == 2) ? 1024 : 2048;
        for (int i = t; i < 2048; i += T) hist[i] = 0u;
        __syncthreads();
        unsigned pfx = shPrefix, msk = shMask;
        for (int j = t; j < Q; j += T) {
            unsigned u = orderedKey(cert[j]);
            if ((u & msk) == pfx) atomicAdd(&hist[(u >> shift) & (nb - 1)], 1u);
        }
        __syncthreads();
        if (t == 0) {
            int rem = shRem;
            unsigned acc = 0;
            int b;
            for (b = nb - 1; b >= 0; b--) {
                unsigned h = hist[b];
                if (acc + h >= (unsigned)rem) break;
                acc += h;
            }
            if (b < 0) b = 0;
            shPrefix = pfx | ((unsigned)b << shift);
            shMask = msk | ((unsigned)(nb - 1) << shift);
            shRem = rem - (int)acc;
        }
        __syncthreads();
    }
    unsigned Kkey = shPrefix;
    int rem = shRem;

    __shared__ int eqBase, selBase;
    if (t == 0) { eqBase = 0; selBase = 0; }
    __syncthreads();
    for (int j0 = 0; j0 < Q; j0 += T) {
        int j = j0 + t;
        int isGt = 0, isEq = 0;
        float v = 0.f;
        if (j < Q) {
            v = cert[j];
            unsigned u = orderedKey(v);
            isGt = (u > Kkey);
            isEq = (u == Kkey);
        }
        int eqTot;
        int eqEx = blockScan1024(isEq, &eqTot, ws);
        int sel = isGt | (isEq & ((eqBase + eqEx) < rem));
        int sTot;
        int sEx = blockScan1024(sel, &sTot, ws);
        if (sel) {
            int slot = selBase + sEx;
            selIdx[slot] = j;
            selVal[slot] = v;
        }
        __syncthreads();
        if (t == 0) { eqBase += eqTot; selBase += sTot; }
        __syncthreads();
    }
    if (t == 0) *selK = k;
}

// ----------------------------------------------------------------------------
// K7: pseudo labels (argmax over classes of scaled logits row)
// ----------------------------------------------------------------------------
__global__ void k_pseudo(const float* __restrict__ C, const float* __restrict__ sc,
                         const int* __restrict__ map, const int* __restrict__ selIdx,
                         const int* __restrict__ selK, int* __restrict__ pseudo)
{
    int i = blockIdx.x * blockDim.x + threadIdx.x;
    if (i >= *selK) return;
    int j = selIdx[i];
    int r = map ? map[j] : j;
    const float* row = C + (size_t)r * WAY;
    float best = -3.4e38f;
    int bc = 0;
    for (int c = 0; c < WAY; c++) {
        float v = row[c] * sc[c];
        if (v > best) { best = v; bc = c; }
    }
    pseudo[i] = bc;
}

// ----------------------------------------------------------------------------
// K8: refined proto: P1[c,:] = P0[c,:] + sum_{i: pseudo_i==c} val_i/(K*qn) * A[q_i,:]
// ----------------------------------------------------------------------------
__global__ void k_proto1(const float* __restrict__ P0, const float* __restrict__ A,
                         const float* __restrict__ qn, const int* __restrict__ map,
                         const int* __restrict__ selIdx, const float* __restrict__ selVal,
                         const int* __restrict__ selK, const int* __restrict__ pseudo,
                         float* __restrict__ P1)
{
    int c = blockIdx.x;
    __shared__ int sPse[KSEL];
    __shared__ int sQ[KSEL];
    __shared__ float sCoef[KSEL];
    int K = *selK;
    for (int i = threadIdx.x; i < K; i += 256) {
        int j = selIdx[i];
        int gq = map ? map[j] : j;
        sPse[i] = pseudo[i];
        sQ[i] = gq;
        sCoef[i] = selVal[i] / ((float)K * qn[gq]);
    }
    __syncthreads();
    for (int d = threadIdx.x; d < DIM; d += 256) {
        float acc = P0[(size_t)c * DIM + d];
        for (int i = 0; i < K; i++)
            if (sPse[i] == c) acc += sCoef[i] * A[(size_t)sQ[i] * DIM + d];
        P1[(size_t)c * DIM + d] = acc;
    }
}

// ----------------------------------------------------------------------------
// K9: per-row softmax stats (abs_c = row max, rel_c = sum p*log(p+1e-10))
// ----------------------------------------------------------------------------
__global__ void k_rowstats(const float* __restrict__ C, const float* __restrict__ sc,
                           const int* __restrict__ cnt,
                           float* __restrict__ absc, float* __restrict__ relc)
{
    int warp = (blockIdx.x * blockDim.x + threadIdx.x) >> 5;
    int lane = threadIdx.x & 31;
    if (warp >= *cnt) return;
    const float* row = C + (size_t)warp * WAY;
    float m = -3.4e38f;
    for (int c = lane; c < WAY; c += 32) m = fmaxf(m, row[c] * sc[c]);
    #pragma unroll
    for (int o = 16; o > 0; o >>= 1) m = fmaxf(m, __shfl_xor_sync(0xffffffffu, m, o));
    float Z = 0.f;
    for (int c = lane; c < WAY; c += 32) Z += expf(row[c] * sc[c] - m);
    #pragma unroll
    for (int o = 16; o > 0; o >>= 1) Z += __shfl_xor_sync(0xffffffffu, Z, o);
    float rel = 0.f;
    for (int c = lane; c < WAY; c += 32) {
        float p = expf(row[c] * sc[c] - m) / Z;
        rel += p * logf(p + 1e-10f);
    }
    #pragma unroll
    for (int o = 16; o > 0; o >>= 1) rel += __shfl_xor_sync(0xffffffffu, rel, o);
    if (lane == 0) { absc[warp] = m; relc[warp] = rel; }
}

// ----------------------------------------------------------------------------
// K10: partition by diff sign, stable order; writes index lists + out floats
// ----------------------------------------------------------------------------
__global__ __launch_bounds__(1024) void k_partition(
    const float* __restrict__ ar, const float* __restrict__ ad,
    const float* __restrict__ rr, const float* __restrict__ rd,
    int* __restrict__ resIdx, int* __restrict__ dctIdx,
    int* __restrict__ cnts, float* __restrict__ out)
{
    const int T = 1024;
    int t = threadIdx.x;
    __shared__ int ws[32];
    __shared__ int runBase;
    __shared__ int Rsh;
    if (t == 0) runBase = 0;
    __syncthreads();
    // pass 1: diff > 0 -> res
    for (int j0 = 0; j0 < NQ; j0 += T) {
        int j = j0 + t;
        int f = 0;
        if (j < NQ) {
            float diff = ar[j] - ad[j] + rr[j] - rd[j];
            f = (diff > 0.f);
        }
        int tot;
        int ex = blockScan1024(f, &tot, ws);
        if (f) {
            int slot = runBase + ex;
            resIdx[slot] = j;
            out[2 + slot] = (float)j;
        }
        __syncthreads();
        if (t == 0) runBase += tot;
        __syncthreads();
    }
    if (t == 0) { Rsh = runBase; cnts[0] = runBase; runBase = 0; }
    __syncthreads();
    int R = Rsh;
    // pass 2: diff < 0 -> dct
    for (int j0 = 0; j0 < NQ; j0 += T) {
        int j = j0 + t;
        int f = 0;
        if (j < NQ) {
            float diff = ar[j] - ad[j] + rr[j] - rd[j];
            f = (diff < 0.f);
        }
        int tot;
        int ex = blockScan1024(f, &tot, ws);
        if (f) {
            int slot = runBase + ex;
            dctIdx[slot] = j;
            out[2 + R + slot] = (float)j;
        }
        __syncthreads();
        if (t == 0) runBase += tot;
        __syncthreads();
    }
    if (t == 0) cnts[1] = runBase;
}

// ----------------------------------------------------------------------------
// K11: confidence weights
// ----------------------------------------------------------------------------
__global__ void k_w(const float* __restrict__ ar, const float* __restrict__ ad,
                    const int* __restrict__ cnts, float* __restrict__ out)
{
    int q = blockIdx.x * blockDim.x + threadIdx.x;
    if (q >= NQ) return;
    int base = 2 + cnts[0] + cnts[1];
    float a = ar[q], b = ad[q];
    float den = fmaxf(a + b, 1e-8f);
    out[base + q] = a / den;
    out[base + NQ + q] = b / den;
}

// ----------------------------------------------------------------------------
// K12: per-class KL sum over the query dim (softmax over queries per class)
// ----------------------------------------------------------------------------
__global__ void k_classkl(const float* __restrict__ Lh, const float* __restrict__ sch,
                          const float* __restrict__ Ll, const float* __restrict__ scl,
                          const int* __restrict__ cnt, float* __restrict__ kl)
{
    int c = blockIdx.x;
    int Q = *cnt;
    float sh = sch[c], sl = scl[c];
    __shared__ float red[256];
    float mh = -3.4e38f, ml = -3.4e38f;
    for (int j = threadIdx.x; j < Q; j += 256) {
        mh = fmaxf(mh, Lh[(size_t)j * WAY + c] * sh);
        ml = fmaxf(ml, Ll[(size_t)j * WAY + c] * sl);
    }
    mh = blockReduceMax256(mh, red);
    ml = blockReduceMax256(ml, red);
    float Zh = 0.f, Zl = 0.f;
    for (int j = threadIdx.x; j < Q; j += 256) {
        Zh += expf(Lh[(size_t)j * WAY + c] * sh - mh);
        Zl += expf(Ll[(size_t)j * WAY + c] * sl - ml);
    }
    Zh = blockReduceSum256(Zh, red);
    Zl = blockReduceSum256(Zl, red);
    float lZl = logf(Zl);
    float s = 0.f;
    for (int j = threadIdx.x; j < Q; j += 256) {
        float lh = Lh[(size_t)j * WAY + c] * sh;
        float ll = Ll[(size_t)j * WAY + c] * sl;
        float p = expf(lh - mh) / Zh;
        s += p * (logf(p) - (ll - ml - lZl));
    }
    s = blockReduceSum256(s, red);
    if (threadIdx.x == 0) kl[c] = s;
}

// ----------------------------------------------------------------------------
// K13: finalize loss = w0 * sum(kl) / (sum_w + 1e-8) * tempScalar
// ----------------------------------------------------------------------------
__global__ void k_finalize(const float* __restrict__ kl, const float* __restrict__ absc,
                           const int* __restrict__ subsetIdx, const int* __restrict__ cnt,
                           const float* __restrict__ tempScalar, float* __restrict__ outSlot)
{
    __shared__ float red[256];
    int Q = *cnt;
    float s = 0.f;
    for (int c = threadIdx.x; c < WAY; c += 256) s += kl[c];
    s = blockReduceSum256(s, red);
    float sw = 0.f;
    for (int j = threadIdx.x; j < Q; j += 256) sw += absc[subsetIdx[j]];
    sw = blockReduceSum256(sw, red);
    if (threadIdx.x == 0) {
        float w0 = (Q > 0) ? absc[subsetIdx[0]] : 0.f;
        float loss = w0 * s / (sw + 1e-8f);
        *outSlot = (*tempScalar) * loss;
    }
}

// ----------------------------------------------------------------------------
// Host-side orchestration
// ----------------------------------------------------------------------------
struct Ptrs {
    float *P0R, *P0D, *P1, *QNR, *QND, *GR, *GD, *G2, *LH, *LL;
    float *CERT, *SELV, *ABSR, *ABSD, *RELR, *RELD;
    float *CN1, *SC1, *CN2, *SC2, *SCH, *SCL, *KL;
    int *RES, *DCT, *SELI, *PSE, *SELK, *CNTS;
    int *FULLCNT;
    const float *tp;
};

// run the "distance tail": from a precomputed proto0-GEMM G + map/cnt
// to final (raw logits2 in Lout, scale in scOut)
static void distance_tail(const Ptrs& p,
                          const float* A, const float* qn, const float* P0,
                          const float* G, const int* map, const int* cnt,
                          float* Lout, float* scOut)
{
    k_colnorm<<<WAY, 256>>>(G, map, cnt, p.CN1);
    k_scale<<<1, 128>>>(p.CN1, p.tp, p.SC1);
    k_cert<<<(NQ + 255) / 256, 256>>>(G, p.SC1, map, cnt, p.CERT);
    k_topk<<<1, 1024>>>(p.CERT, cnt, p.SELI, p.SELV, p.SELK);
    k_pseudo<<<2, 256>>>(G, p.SC1, map, p.SELI, p.SELK, p.PSE);
    k_proto1<<<WAY, 256>>>(P0, A, qn, map, p.SELI, p.SELV, p.SELK, p.PSE, p.P1);
    k_gemm<<<(NQ + G_TQ - 1) / G_TQ, 256>>>(A, qn, p.P1, Lout, map, cnt);
    k_colnorm<<<WAY, 256>>>(Lout, nullptr, cnt, p.CN2);
    k_scale<<<1, 128>>>(p.CN2, p.tp, scOut);
}

extern "C" void kernel_launch(void* const* d_in, const int* in_sizes, int n_in,
                              void* d_out, int out_size)
{
    const float* x_shot    = (const float*)d_in[0];
    const float* x_query   = (const float*)d_in[1];
    const float* dct_shot  = (const float*)d_in[2];
    const float* dct_query = (const float*)d_in[3];
    const float* tp        = (const float*)d_in[4];
    const float* temp      = (const float*)d_in[5];
    const float* temp_dct  = (const float*)d_in[6];
    float* out = (float*)d_out;

    float* B = nullptr;
    int* IB = nullptr;
    int* FC = nullptr;
    cudaGetSymbolAddress((void**)&B, g_buf);
    cudaGetSymbolAddress((void**)&IB, g_ibuf);
    cudaGetSymbolAddress((void**)&FC, g_fullCnt);

    Ptrs p;
    p.P0R = B + O_P0R; p.P0D = B + O_P0D; p.P1 = B + O_P1;
    p.QNR = B + O_QNR; p.QND = B + O_QND;
    p.GR = B + O_GR; p.GD = B + O_GD; p.G2 = B + O_G2;
    p.LH = B + O_LH; p.LL = B + O_LL;
    p.CERT = B + O_CERT; p.SELV = B + O_SELV;
    p.ABSR = B + O_ABSR; p.ABSD = B + O_ABSD;
    p.RELR = B + O_RELR; p.RELD = B + O_RELD;
    p.CN1 = B + O_CN1; p.SC1 = B + O_SC1; p.CN2 = B + O_CN2; p.SC2 = B + O_SC2;
    p.SCH = B + O_SCH; p.SCL = B + O_SCL; p.KL = B + O_KL;
    p.RES = IB + IO_RES; p.DCT = IB + IO_DCT; p.SELI = IB + IO_SELI;
    p.PSE = IB + IO_PSE; p.SELK = IB + IO_SELK; p.CNTS = IB + IO_CNTS;
    p.FULLCNT = FC;
    p.tp = tp;

    const int GEMM_GRID = (NQ + G_TQ - 1) / G_TQ;

    // ---- full pipeline, stream r ----
    k_proto0<<<WAY, 256>>>(x_shot, p.P0R);
    k_qnorm<<<NQ, 256>>>(x_query, p.QNR);
    k_gemm<<<GEMM_GRID, 256>>>(x_query, p.QNR, p.P0R, p.GR, nullptr, p.FULLCNT);
    distance_tail(p, x_query, p.QNR, p.P0R, p.GR, nullptr, p.FULLCNT, p.G2, p.SC2);
    k_rowstats<<<(NQ * 32 + 255) / 256, 256>>>(p.G2, p.SC2, p.FULLCNT, p.ABSR, p.RELR);

    // ---- full pipeline, stream d ----
    k_proto0<<<WAY, 256>>>(dct_shot, p.P0D);
    k_qnorm<<<NQ, 256>>>(dct_query, p.QND);
    k_gemm<<<GEMM_GRID, 256>>>(dct_query, p.QND, p.P0D, p.GD, nullptr, p.FULLCNT);
    distance_tail(p, dct_query, p.QND, p.P0D, p.GD, nullptr, p.FULLCNT, p.G2, p.SC2);
    k_rowstats<<<(NQ * 32 + 255) / 256, 256>>>(p.G2, p.SC2, p.FULLCNT, p.ABSD, p.RELD);

    // ---- partition + weights ----
    k_partition<<<1, 1024>>>(p.ABSR, p.ABSD, p.RELR, p.RELD, p.RES, p.DCT, p.CNTS, out);
    k_w<<<(NQ + 255) / 256, 256>>>(p.ABSR, p.ABSD, p.CNTS, out);

    const int* CR = p.CNTS + 0;  // R
    const int* CD = p.CNTS + 1;  // D

    // ---- loss_dctl: lrh (x on res, high), ldl (dct on res, low), weight abs_c[res] ----
    distance_tail(p, x_query, p.QNR, p.P0R, p.GR, p.RES, CR, p.LH, p.SCH);
    distance_tail(p, dct_query, p.QND, p.P0D, p.GD, p.RES, CR, p.LL, p.SCL);
    k_classkl<<<WAY, 256>>>(p.LH, p.SCH, p.LL, p.SCL, CR, p.KL);
    k_finalize<<<1, 256>>>(p.KL, p.ABSR, p.RES, CR, temp_dct, out + 1);

    // ---- loss_resl: ldh (dct on dct, high), lrl (x on dct, low), weight abs_cd[dct] ----
    distance_tail(p, dct_query, p.QND, p.P0D, p.GD, p.DCT, CD, p.LH, p.SCH);
    distance_tail(p, x_query, p.QNR, p.P0R, p.GR, p.DCT, CD, p.LL, p.SCL);
    k_classkl<<<WAY, 256>>>(p.LH, p.SCH, p.LL, p.SCL, CD, p.KL);
    k_finalize<<<1, 256>>>(p.KL, p.ABSD, p.DCT, CD, temp, out + 0);
}